// round 16
// baseline (speedup 1.0000x reference)
#include <cuda_runtime.h>
#include <cstdint>

#define TPB  128
#define SO   128       // outputs (rows) per block
#define M    11
#define T    4096
#define BB   32
#define NA   148       // Ak window entries: position t0+i-20, i in [0,148)
#define NU   138       // U entries: u(t0+i-10), i in [0,138)
#define AKS  152       // per-k stride in AkF
#define BST  24        // Bs row stride
#define SST  18        // Ssm row stride

__device__ __forceinline__ float tf32r(float x) {
    float y;
    asm("cvt.rna.tf32.f32 %0, %1;" : "=f"(y) : "f"(x));
    return y;
}

__device__ __forceinline__ void mma_tf32(float d[4], const uint32_t a[4], const uint32_t b[2]) {
    asm volatile(
        "mma.sync.aligned.m16n8k8.row.col.f32.tf32.tf32.f32 "
        "{%0,%1,%2,%3}, {%4,%5,%6,%7}, {%8,%9}, {%0,%1,%2,%3};"
        : "+f"(d[0]), "+f"(d[1]), "+f"(d[2]), "+f"(d[3])
        : "r"(a[0]), "r"(a[1]), "r"(a[2]), "r"(a[3]), "r"(b[0]), "r"(b[1]));
}

__global__ void __launch_bounds__(TPB)
gmp_kernel(const float2* __restrict__ x,
           const float*  __restrict__ W,
           float2* __restrict__ out)
{
    __shared__ __align__(16) float  AkF[4 * AKS];  // tf32(|u(t0+i-20)|^(k+1))
    __shared__ __align__(16) float2 U[NU + 2];     // fp32 samples (epilogue)
    __shared__ __align__(16) float  Bs[88 * BST];  // Bh[r][m], r = k*22+d
    __shared__ float  w0s[M];
    __shared__ __align__(16) float  Ssm[SO * SST]; // S[t][m] after GEMM (float2-stored!)

    const int b    = blockIdx.y;
    const int t0   = blockIdx.x * SO;
    const int tid  = threadIdx.x;
    const int warp = tid >> 5;
    const int lane = tid & 31;
    const int qid  = lane >> 2;            // fragment row group 0..7
    const int qlan = lane & 3;             // fragment col group 0..3
    const float2* xb = x + (size_t)b * T;

    // ---- stage amplitude powers (tf32-pre-rounded) + samples ----
    for (int i = tid; i < NA; i += TPB) {
        int pos = t0 + i - 20;
        float re = 0.f, im = 0.f;
        if (pos >= 0) { float2 v = xb[pos]; re = v.x; im = v.y; }
        float a2 = re * re + im * im;
        float a  = sqrtf(a2);
        AkF[0 * AKS + i] = tf32r(a);
        AkF[1 * AKS + i] = tf32r(a2);
        AkF[2 * AKS + i] = tf32r(a2 * a);
        AkF[3 * AKS + i] = tf32r(a2 * a2);
        if (i >= 10) U[i - 10] = make_float2(re, im);
    }
    // ---- build Bh[r][m] = W1[k][d-m][m] if 0<=d-m<=10 else 0 ----
    for (int r = tid; r < 88; r += TPB) {
        int k = r / 22, d = r % 22;
#pragma unroll
        for (int m = 0; m < 16; m++) {
            float v = 0.f;
            int l = d - m;
            if (m < M && l >= 0 && l <= 10) v = W[11 + k * 121 + l * 11 + m];
            Bs[r * BST + m] = tf32r(v);
        }
    }
    if (tid < M) w0s[tid] = W[tid];
    __syncthreads();

    // ---- GEMM: warp computes rows [warp*32, warp*32+32) x 16 cols, K=88 ----
    float acc[2][2][4];
#pragma unroll
    for (int mt = 0; mt < 2; mt++)
#pragma unroll
        for (int nt = 0; nt < 2; nt++)
#pragma unroll
            for (int i = 0; i < 4; i++) acc[mt][nt][i] = 0.f;

#pragma unroll
    for (int kt = 0; kt < 11; kt++) {
        int r0 = 8 * kt + qlan;           // fragment k-cols
        int r1 = r0 + 4;
        int k0 = (r0 >= 66) ? 3 : (r0 >= 44) ? 2 : (r0 >= 22) ? 1 : 0;
        int k1 = (r1 >= 66) ? 3 : (r1 >= 44) ? 2 : (r1 >= 22) ? 1 : 0;
        int off0 = r0 + 130 * k0;         // AkF index = t_local + d + k*152
        int off1 = r1 + 130 * k1;

        uint32_t afr[2][4];
#pragma unroll
        for (int mt = 0; mt < 2; mt++) {
            int base = warp * 32 + mt * 16 + qid;
            afr[mt][0] = __float_as_uint(AkF[base + off0]);
            afr[mt][1] = __float_as_uint(AkF[base + 8 + off0]);
            afr[mt][2] = __float_as_uint(AkF[base + off1]);
            afr[mt][3] = __float_as_uint(AkF[base + 8 + off1]);
        }
        uint32_t bfr[2][2];
        int br0 = r0 * BST + qid;
        int br1 = r1 * BST + qid;
        bfr[0][0] = __float_as_uint(Bs[br0]);
        bfr[0][1] = __float_as_uint(Bs[br1]);
        bfr[1][0] = __float_as_uint(Bs[br0 + 8]);
        bfr[1][1] = __float_as_uint(Bs[br1 + 8]);

#pragma unroll
        for (int mt = 0; mt < 2; mt++)
#pragma unroll
            for (int nt = 0; nt < 2; nt++)
                mma_tf32(acc[mt][nt], afr[mt], bfr[nt]);
    }

    // ---- spill S to smem (C fragment: rows qid/qid+8, cols 2*qlan..) ----
#pragma unroll
    for (int mt = 0; mt < 2; mt++) {
#pragma unroll
        for (int nt = 0; nt < 2; nt++) {
            int row = warp * 32 + mt * 16 + qid;
            int col = nt * 8 + qlan * 2;
            *(float2*)&Ssm[row * SST + col]       = make_float2(acc[mt][nt][0], acc[mt][nt][1]);
            *(float2*)&Ssm[(row + 8) * SST + col] = make_float2(acc[mt][nt][2], acc[mt][nt][3]);
        }
    }
    __syncthreads();

    // ---- epilogue (fp32): out(t) = sum_m u(t+m-10) * (W0[m] + S[t,m]) ----
    {
        const int t = tid;
        float ar = 0.f, ai = 0.f;
#pragma unroll
        for (int m = 0; m < M; m++) {
            float cm = Ssm[t * SST + m] + w0s[m];
            float2 u = U[t + m];
            ar = fmaf(u.x, cm, ar);
            ai = fmaf(u.y, cm, ai);
        }
        out[(size_t)b * T + t0 + t] = make_float2(ar, ai);
    }
}

extern "C" void kernel_launch(void* const* d_in, const int* in_sizes, int n_in,
                              void* d_out, int out_size)
{
    const float2* x = (const float2*)d_in[0];   // (32, 4096, 2) f32
    // d_in[1] = h_0 (unused by reference)
    const float*  W = (const float*)d_in[2];    // (1, 495) f32
    float2* out = (float2*)d_out;               // (32, 4096, 2) f32

    dim3 grid(T / SO, BB);                      // (32, 32) = 1024 blocks
    gmp_kernel<<<grid, TPB>>>(x, W, out);
}